// round 14
// baseline (speedup 1.0000x reference)
#include <cuda_runtime.h>
#include <cuda_bf16.h>
#include <cuda_fp16.h>
#include <cstdint>

typedef unsigned long long ull;

// ================= constants =================
#define TT    4096
#define NQ    12288
#define CONVD 8192
#define CH    64
#define NCH   64
#define HVN   32
#define LDA   132
#define LDT   65
#define LDS33 33
#define LDAT  68

// ================= device scratch =================
__device__ float g_qkvz[(size_t)TT * NQ];
__device__ float g_ba[TT * 64];
__device__ float g_y[(size_t)CONVD * TT];
__device__ float g_beta[HVN * TT];
__device__ float g_gc[HVN * TT];
__device__ float g_glast[HVN * NCH];
__device__ float g_u [(size_t)HVN * TT * 128];
__device__ float g_w [(size_t)HVN * TT * 128];
__device__ float g_qg[(size_t)HVN * TT * 128];
__device__ float g_kd[(size_t)HVN * TT * 128];
__device__ float g_attn[(size_t)HVN * NCH * CH * CH];
__device__ float g_o [(size_t)TT * 4096];
// fp16 operands for 2-term split GEMMs
__device__ __half g_xf [(size_t)TT * 2048];
__device__ __half g_wqh[(size_t)NQ * 2048];
__device__ __half g_wql[(size_t)NQ * 2048];
__device__ __half g_woh[(size_t)2048 * 4096];
__device__ __half g_wol[(size_t)2048 * 4096];
__device__ __half g_ogf[(size_t)TT * 4096];

// ================= PTX helpers =================
__device__ __forceinline__ uint32_t s2u(const void* p) {
    uint32_t a;
    asm("{ .reg .u64 t; cvta.to.shared.u64 t, %1; cvt.u32.u64 %0, t; }" : "=r"(a) : "l"(p));
    return a;
}
__device__ __forceinline__ void cpa16(uint32_t d, const void* s) {
    asm volatile("cp.async.cg.shared.global [%0], [%1], 16;" :: "r"(d), "l"(s) : "memory");
}
#define CPA_COMMIT() asm volatile("cp.async.commit_group;" ::: "memory")
__device__ __forceinline__ void ldm_x4(uint32_t* r, uint32_t a) {
    asm volatile("ldmatrix.sync.aligned.m8n8.x4.shared.b16 {%0,%1,%2,%3}, [%4];"
                 : "=r"(r[0]), "=r"(r[1]), "=r"(r[2]), "=r"(r[3]) : "r"(a));
}
__device__ __forceinline__ void mma16816h(float* d, const uint32_t* a, const uint32_t* b) {
    asm volatile("mma.sync.aligned.m16n8k16.row.col.f32.f16.f16.f32 "
                 "{%0,%1,%2,%3}, {%4,%5,%6,%7}, {%8,%9}, {%0,%1,%2,%3};"
                 : "+f"(d[0]), "+f"(d[1]), "+f"(d[2]), "+f"(d[3])
                 : "r"(a[0]), "r"(a[1]), "r"(a[2]), "r"(a[3]), "r"(b[0]), "r"(b[1]));
}
__device__ __forceinline__ ull pk2(float lo, float hi) {
    ull r;
    asm("mov.b64 %0, {%1, %2};" : "=l"(r) : "f"(lo), "f"(hi));
    return r;
}
__device__ __forceinline__ float2 upk2(ull v) {
    float2 r;
    asm("mov.b64 {%0, %1}, %2;" : "=f"(r.x), "=f"(r.y) : "l"(v));
    return r;
}
__device__ __forceinline__ void fma2(ull &d, ull a, ull b) {
    asm("fma.rn.f32x2 %0, %1, %2, %0;" : "+l"(d) : "l"(a), "l"(b));
}
__device__ __forceinline__ ull mul2(ull a, ull b) {
    ull r;
    asm("mul.rn.f32x2 %0, %1, %2;" : "=l"(r) : "l"(a), "l"(b));
    return r;
}

// ================= hgemm2 v5: fp16 2-term, CTA 128x256, 512 thr, BK=64, 2-stage =================
#define HG_STRIDE 72                         // 64 + 8 pad; conflict-free ldmatrix (16B-bank offset 16*r)
#define HG_A_BYTES (128 * HG_STRIDE * 2)     // 18432
#define HG_B_BYTES (256 * HG_STRIDE * 2)     // 36864
#define HG_OFF_BH  HG_A_BYTES                // 18432
#define HG_OFF_BL  (HG_OFF_BH + HG_B_BYTES)  // 55296
#define HG_STAGE_BYTES (HG_OFF_BL + HG_B_BYTES)  // 92160
#define HG_SMEM (2 * HG_STAGE_BYTES)         // 184320

__device__ __forceinline__ void hg_stage_load(uint32_t sb,
                                              const __half* __restrict__ Af,
                                              const __half* __restrict__ Bh,
                                              const __half* __restrict__ Bl,
                                              int m0, int n0, int K, int k0, int tid) {
    // A: 128 rows x 64 k = 1024 16B-tasks → 2 per thread
#pragma unroll
    for (int i = 0; i < 2; i++) {
        int idx = tid + i * 512;
        int r = idx >> 3, q = (idx & 7) * 8;
        uint32_t so = (uint32_t)(r * HG_STRIDE + q) * 2;
        cpa16(sb + so, Af + (size_t)(m0 + r) * K + k0 + q);
    }
    // B hi/lo: 256 rows x 64 k = 2048 tasks each → 4 per thread each
#pragma unroll
    for (int i = 0; i < 4; i++) {
        int idx = tid + i * 512;
        int r = idx >> 3, q = (idx & 7) * 8;
        uint32_t so = (uint32_t)(r * HG_STRIDE + q) * 2;
        cpa16(sb + HG_OFF_BH + so, Bh + (size_t)(n0 + r) * K + k0 + q);
        cpa16(sb + HG_OFF_BL + so, Bl + (size_t)(n0 + r) * K + k0 + q);
    }
    CPA_COMMIT();
}

__global__ void __launch_bounds__(512, 1) hgemm2(const __half* __restrict__ Af,
                                                 const __half* __restrict__ Bh,
                                                 const __half* __restrict__ Bl,
                                                 float* __restrict__ C,
                                                 int M, int N, int K) {
    extern __shared__ __align__(16) char hsm[];
    uint32_t sbase = s2u(hsm);
    int tid = threadIdx.x, lane = tid & 31, wid = tid >> 5;
    int wm = wid >> 3, wn = wid & 7;          // 2 x 8 warps, warp tile 64 x 32
    int m0 = blockIdx.y * 128, n0 = blockIdx.x * 256;

    float acc[4][4][4];
#pragma unroll
    for (int a = 0; a < 4; a++)
#pragma unroll
        for (int b = 0; b < 4; b++)
#pragma unroll
            for (int c = 0; c < 4; c++) acc[a][b][c] = 0.f;

    int NCC = K >> 6;                         // BK = 64
    hg_stage_load(sbase, Af, Bh, Bl, m0, n0, K, 0, tid);

    int arow = wm * 64 + (lane & 15);
    int acol = (lane >> 4) << 3;
    int brow = wn * 32 + (lane & 7) + ((lane >> 4) << 3);
    int bcol = ((lane >> 3) & 1) << 3;

    for (int c = 0; c < NCC; c++) {
        // pending = load(c) only → full drain retires exactly the stage we need
        asm volatile("cp.async.wait_group 0;" ::: "memory");
        __syncthreads();   // all threads see stage c; compute(c-1) reads of the other buffer retired

        // prefetch next stage into the other buffer (safe: last reader finished before the sync above)
        if (c + 1 < NCC)
            hg_stage_load(sbase + ((c + 1) & 1) * HG_STAGE_BYTES, Af, Bh, Bl,
                          m0, n0, K, (c + 1) << 6, tid);

        uint32_t sb = sbase + (c & 1) * HG_STAGE_BYTES;
#pragma unroll
        for (int kc = 0; kc < 64; kc += 16) {
            uint32_t af[4][4], bh[4][2], bl[4][2];
#pragma unroll
            for (int mt = 0; mt < 4; mt++) {
                uint32_t ad = sb + (uint32_t)((arow + mt * 16) * HG_STRIDE + kc + acol) * 2;
                ldm_x4(af[mt], ad);
            }
#pragma unroll
            for (int j = 0; j < 2; j++) {
                uint32_t bd = sb + HG_OFF_BH + (uint32_t)((brow + j * 16) * HG_STRIDE + kc + bcol) * 2;
                ldm_x4(&bh[2 * j][0], bd);
                ldm_x4(&bl[2 * j][0], bd + HG_B_BYTES);
            }
#pragma unroll
            for (int mt = 0; mt < 4; mt++)
#pragma unroll
                for (int nt = 0; nt < 4; nt++) mma16816h(acc[mt][nt], af[mt], bh[nt]);
#pragma unroll
            for (int mt = 0; mt < 4; mt++)
#pragma unroll
                for (int nt = 0; nt < 4; nt++) mma16816h(acc[mt][nt], af[mt], bl[nt]);
        }
    }

#pragma unroll
    for (int mt = 0; mt < 4; mt++)
#pragma unroll
        for (int nt = 0; nt < 4; nt++) {
            int row = m0 + wm * 64 + mt * 16 + (lane >> 2);
            int col = n0 + wn * 32 + nt * 8 + (lane & 3) * 2;
            *(float2*)&C[(size_t)row * N + col]       = make_float2(acc[mt][nt][0], acc[mt][nt][1]);
            *(float2*)&C[(size_t)(row + 8) * N + col] = make_float2(acc[mt][nt][2], acc[mt][nt][3]);
        }
}

// ================= convert / transpose-split =================
__global__ void conv_fp16_kernel(const float* __restrict__ src, __half* __restrict__ dst) {
    size_t i = (size_t)blockIdx.x * 256 + threadIdx.x;
    dst[i] = __float2half(src[i]);
}

__global__ void tsplit_kernel(const float* __restrict__ W, __half* __restrict__ Th,
                              __half* __restrict__ Tl, int R, int Ccols) {
    __shared__ float t[32][33];
    int c0 = blockIdx.x * 32, rr0 = blockIdx.y * 32;
    int tx = threadIdx.x;
    for (int j = threadIdx.y; j < 32; j += 8)
        t[j][tx] = W[(size_t)(rr0 + j) * Ccols + c0 + tx];
    __syncthreads();
    for (int j = threadIdx.y; j < 32; j += 8) {
        float v = t[tx][j];
        __half hi = __float2half(v);
        size_t o = (size_t)(c0 + j) * R + rr0 + tx;
        Th[o] = hi;
        Tl[o] = __float2half(v - __half2float(hi));
    }
}

// ================= ba = x @ W_ba =================
__global__ void __launch_bounds__(256) gemm_ba(const float* __restrict__ x, const float* __restrict__ W) {
    __shared__ float xs[16][33];
    __shared__ float Ws[32][65];
    int t0 = blockIdx.x * 16;
    int tid = threadIdx.x;
    int cb = tid & 63;
    int rg = tid >> 6;
    float acc[4] = {0.f, 0.f, 0.f, 0.f};

    for (int k0 = 0; k0 < 2048; k0 += 32) {
        for (int idx = tid; idx < 512; idx += 256) {
            int r = idx >> 5, k = idx & 31;
            xs[r][k] = x[(size_t)(t0 + r) * 2048 + k0 + k];
        }
        for (int idx = tid; idx < 2048; idx += 256) {
            int k = idx >> 6, j = idx & 63;
            Ws[k][j] = W[(size_t)(k0 + k) * 64 + j];
        }
        __syncthreads();
#pragma unroll 8
        for (int k = 0; k < 32; k++) {
            float wv = Ws[k][cb];
#pragma unroll
            for (int r = 0; r < 4; r++)
                acc[r] += xs[rg * 4 + r][k] * wv;
        }
        __syncthreads();
    }
#pragma unroll
    for (int r = 0; r < 4; r++)
        g_ba[(t0 + rg * 4 + r) * 64 + cb] = acc[r];
}

// ================= causal depthwise conv + SiLU (4 outputs/thread) =================
__global__ void conv_kernel(const float* __restrict__ conv_w) {
    int base = (blockIdx.x * 256 + threadIdx.x) * 4;
    int j = base >> 12;
    int p = base & 4095;
    float w0 = conv_w[j * 4 + 0];
    float w1 = conv_w[j * 4 + 1];
    float w2 = conv_w[j * 4 + 2];
    float w3 = conv_w[j * 4 + 3];
    float in[7];
#pragma unroll
    for (int m = 0; m < 7; m++) {
        int pos = p - 3 + m;
        if (pos >= 0) {
            int s = base - 3 + m;
            int h = s >> 21;
            int t = (s >> 9) & 4095;
            int c = s & 511;
            in[m] = g_qkvz[(size_t)t * NQ + h * 768 + c];
        } else in[m] = 0.f;
    }
    float4 out;
    float* po = &out.x;
#pragma unroll
    for (int o = 0; o < 4; o++) {
        float a = w0 * in[o] + w1 * in[o + 1] + w2 * in[o + 2] + w3 * in[o + 3];
        po[o] = a / (1.f + __expf(-a));
    }
    *(float4*)&g_y[base] = out;
}

// ================= beta, g, within-chunk cumsum =================
__global__ void gbeta_kernel(const float* __restrict__ dt_bias, const float* __restrict__ A_log) {
    int n = blockIdx.x, hv = blockIdx.y;
    int i = threadIdx.x;
    int t = n * CH + i;
    int h16 = hv >> 1, r = hv & 1;
    float b = g_ba[t * 64 + h16 * 4 + r];
    float a = g_ba[t * 64 + h16 * 4 + 2 + r];
    float beta = 1.f / (1.f + expf(-b));
    float xx = a + dt_bias[hv];
    float sp = (xx > 20.f) ? xx : log1pf(expf(xx));
    float g = -expf(A_log[hv]) * sp;
    __shared__ float s[64];
    s[i] = g;
    __syncthreads();
#pragma unroll
    for (int off = 1; off < 64; off <<= 1) {
        float v = (i >= off) ? s[i - off] : 0.f;
        __syncthreads();
        s[i] += v;
        __syncthreads();
    }
    g_beta[hv * TT + t] = beta;
    g_gc[hv * TT + t]   = s[i];
    if (i == 63) g_glast[hv * NCH + n] = s[63];
}

// ================= Pass A (R13) =================
#define PA_SMEM ((3*64*LDA + 3*64) * 4)
__global__ void __launch_bounds__(256, 2) passA_kernel() {
    extern __shared__ float sm[];
    float* qs  = sm;
    float* ks  = qs + 64 * LDA;
    float* vs  = ks + 64 * LDA;
    float* gcs = vs + 64 * LDA;
    float* bes = gcs + 64;
    float* wcf = bes + 64;
    float* Mm  = qs;
    float* Ti  = qs + 64 * LDT;

    int n = blockIdx.x, hv = blockIdx.y, h16 = hv >> 1;
    int tid = threadIdx.x;
    int tb = n * CH;

    for (int idx = tid; idx < 8192; idx += 256) {
        int d = idx >> 6, i = idx & 63;
        int t = tb + i;
        qs[i * LDA + d] = g_y[(size_t)(h16 * 128 + d) * TT + t];
        ks[i * LDA + d] = g_y[(size_t)(2048 + h16 * 128 + d) * TT + t];
        vs[i * LDA + d] = g_y[(size_t)(4096 + hv * 128 + d) * TT + t];
    }
    if (tid < 64) {
        gcs[tid] = g_gc[hv * TT + tb + tid];
        bes[tid] = g_beta[hv * TT + tb + tid];
    }
    __syncthreads();
    {
        int row = tid >> 2;
        int d0 = (tid & 3) * 32;
        if (tid < 64) wcf[tid] = bes[tid] * expf(gcs[tid]);
        float sq = 0.f, sk = 0.f;
        for (int d = d0; d < d0 + 32; d += 4) {
            float4 a4 = *(float4*)&qs[row * LDA + d];
            float4 b4 = *(float4*)&ks[row * LDA + d];
            sq += a4.x * a4.x + a4.y * a4.y + a4.z * a4.z + a4.w * a4.w;
            sk += b4.x * b4.x + b4.y * b4.y + b4.z * b4.z + b4.w * b4.w;
        }
        sq += __shfl_xor_sync(0xffffffffu, sq, 1);
        sq += __shfl_xor_sync(0xffffffffu, sq, 2);
        sk += __shfl_xor_sync(0xffffffffu, sk, 1);
        sk += __shfl_xor_sync(0xffffffffu, sk, 2);
        float rq = rsqrtf(sq + 1e-6f) * 0.08838834764831845f;
        float rk = rsqrtf(sk + 1e-6f);
        for (int d = d0; d < d0 + 32; d += 4) {
            float4 a4 = *(float4*)&qs[row * LDA + d];
            float4 b4 = *(float4*)&ks[row * LDA + d];
            a4.x *= rq; a4.y *= rq; a4.z *= rq; a4.w *= rq;
            b4.x *= rk; b4.y *= rk; b4.z *= rk; b4.w *= rk;
            *(float4*)&qs[row * LDA + d] = a4;
            *(float4*)&ks[row * LDA + d] = b4;
        }
    }
    __syncthreads();

    int ti0 = (tid >> 4) * 4;
    int jb  = tid & 15;
    float accK[4][4], accQ[4][4];
    {
        ull aKp[4][4], aQp[4][4];
#pragma unroll
        for (int r = 0; r < 4; r++)
#pragma unroll
            for (int c = 0; c < 4; c++) { aKp[r][c] = 0ull; aQp[r][c] = 0ull; }
        for (int d = 0; d < 128; d += 4) {
            ulonglong2 kj[4], ki[4], qi[4];
#pragma unroll
            for (int c = 0; c < 4; c++) kj[c] = *(ulonglong2*)&ks[(jb + 16 * c) * LDA + d];
#pragma unroll
            for (int r = 0; r < 4; r++) {
                ki[r] = *(ulonglong2*)&ks[(ti0 + r) * LDA + d];
                qi[r] = *(ulonglong2*)&qs[(ti0 + r) * LDA + d];
            }
#pragma unroll
            for (int r = 0; r < 4; r++)
#pragma unroll
                for (int c = 0; c < 4; c++) {
                    fma2(aKp[r][c], ki[r].x, kj[c].x);
                    fma2(aKp[r][c], ki[r].y, kj[c].y);
                    fma2(aQp[r][c], qi[r].x, kj[c].x);
                    fma2(aQp[r][c], qi[r].y, kj[c].y);
                }
        }
#pragma unroll
        for (int r = 0; r < 4; r++)
#pragma unroll
            for (int c = 0; c < 4; c++) {
                float2 pk = upk2(aKp[r][c]); accK[r][c] = pk.x + pk.y;
                float2 pq = upk2(aQp[r][c]); accQ[r][c] = pq.x + pq.y;
            }
#pragma unroll
        for (int r = 0; r < 4; r++)
#pragma unroll
            for (int c = 0; c < 4; c++) {
                int i = ti0 + r, j = jb + 16 * c;
                float dec = (i >= j) ? expf(gcs[i] - gcs[j]) : 0.f;
                g_attn[(((size_t)hv * NCH + n) * CH + i) * CH + j] = (i >= j) ? dec * accQ[r][c] : 0.f;
            }
    }

    float gl = gcs[63];
    for (int idx = tid; idx < 8192; idx += 256) {
        int i = idx >> 7, d = idx & 127;
        size_t ro = ((size_t)hv * TT + tb + i) * 128 + d;
        g_qg[ro] = qs[i * LDA + d] * expf(gcs[i]);
        g_kd[ro] = ks[i * LDA + d] * expf(gl - gcs[i]);
    }
    __syncthreads();

#pragma unroll
    for (int r = 0; r < 4; r++)
#pragma unroll
        for (int c = 0; c < 4; c++) {
            int i = ti0 + r, j = jb + 16 * c;
            float dec = (i > j) ? expf(gcs[i] - gcs[j]) : 0.f;
            Mm[i * LDT + j] = (i > j) ? bes[i] * dec * accK[r][c] : 0.f;
        }
    __syncthreads();

    if (tid < 64) {
        int j = tid;
        for (int i = 0; i < 64; i++) Ti[i * LDT + j] = (i == j) ? 1.f : 0.f;
        for (int i = j + 1; i < 64; i++) {
            float s = 0.f;
            for (int l = j; l < i; l++) s += Mm[i * LDT + l] * Ti[l * LDT + j];
            Ti[i * LDT + j] = -s;
        }
    }
    __syncthreads();

    {
        int i = tid >> 2, d0 = (tid & 3) * 32;
        ull up[16], wp[16];
#pragma unroll
        for (int p = 0; p < 16; p++) { up[p] = 0ull; wp[p] = 0ull; }
        for (int j = 0; j <= i; j++) {
            float tij = Ti[i * LDT + j];
            ull cup = pk2(tij * bes[j], tij * bes[j]);
            ull cwp = pk2(tij * wcf[j], tij * wcf[j]);
#pragma unroll
            for (int q = 0; q < 4; q++) {
                ulonglong2 v2 = *(ulonglong2*)&vs[j * LDA + d0 + q * 4];
                ulonglong2 k2 = *(ulonglong2*)&ks[j * LDA + d0 + q * 4];
                fma2(up[q * 4 + 0], v2.x, cup); fma2(up[q * 4 + 1], v2.y, cup);
                fma2(wp[q * 4 + 0], k2.x, cwp); fma2(wp[q * 4 + 1], k2.y, cwp);
            }
#pragma unroll
            for (int q = 0; q < 4; q++) {
                ulonglong2 v2 = *(ulonglong2*)&vs[j * LDA + d0 + 16 + q * 4];
                ulonglong2 k2 = *(ulonglong2*)&ks[j * LDA + d0 + 16 + q * 4];
                fma2(up[q * 4 + 2], v2.x, cup); fma2(up[q * 4 + 3], v2.y, cup);
                fma2(wp[q * 4 + 2], k2.x, cwp); fma2(wp[q * 4 + 3], k2.y, cwp);
            }
        }
        size_t ro = ((size_t)hv * TT + tb + i) * 128 + d0;
#pragma unroll
        for (int q = 0; q < 4; q++) {
            float2 a0 = upk2(up[q * 4 + 0]), a1 = upk2(up[q * 4 + 1]);
            float2 b0 = upk2(wp[q * 4 + 0]), b1 = upk2(wp[q * 4 + 1]);
            *(float4*)&g_u[ro + q * 4]      = make_float4(a0.x, a0.y, a1.x, a1.y);
            *(float4*)&g_w[ro + q * 4]      = make_float4(b0.x, b0.y, b1.x, b1.y);
            float2 a2 = upk2(up[q * 4 + 2]), a3 = upk2(up[q * 4 + 3]);
            float2 b2 = upk2(wp[q * 4 + 2]), b3 = upk2(wp[q * 4 + 3]);
            *(float4*)&g_u[ro + 16 + q * 4] = make_float4(a2.x, a2.y, a3.x, a3.y);
            *(float4*)&g_w[ro + 16 + q * 4] = make_float4(b2.x, b2.y, b3.x, b3.y);
        }
    }
}

// ================= Scan (R8 proven) =================
#define SC_SMEM ((128*LDS33 + 3*64*LDA + 2*64*LDS33 + 64*LDAT) * 4)
__global__ void __launch_bounds__(256) scan_kernel() {
    extern __shared__ float sm[];
    float* S   = sm;
    float* ws  = S   + 128 * LDS33;
    float* kds = ws  + 64 * LDA;
    float* qgs = kds + 64 * LDA;
    float* us  = qgs + 64 * LDA;
    float* vns = us  + 64 * LDS33;
    float* at  = vns + 64 * LDS33;

    int hv = blockIdx.x >> 2;
    int v0 = (blockIdx.x & 3) * 32;
    int tid = threadIdx.x;
    int vloc = tid & 31;
    int c0 = (tid >> 5) * 8;
    int dk0 = (tid >> 5) * 16;

    for (int idx = tid; idx < 128 * LDS33; idx += 256) S[idx] = 0.f;
    __syncthreads();

    for (int n = 0; n < NCH; n++) {
        size_t base = ((size_t)hv * TT + n * CH) * 128;
        for (int idx4 = tid; idx4 < 2048; idx4 += 256) {
            int i = idx4 >> 5, d4 = (idx4 & 31) * 4;
            *(float4*)&ws [i * LDA + d4] = *(const float4*)&g_w [base + i * 128 + d4];
            *(float4*)&kds[i * LDA + d4] = *(const float4*)&g_kd[base + i * 128 + d4];
            *(float4*)&qgs[i * LDA + d4] = *(const float4*)&g_qg[base + i * 128 + d4];
        }
        for (int idx = tid; idx < 2048; idx += 256) {
            int i = idx >> 5, v = idx & 31;
            us[i * LDS33 + v] = g_u[base + i * 128 + v0 + v];
        }
        for (int idx = tid; idx < 4096; idx += 256) {
            int i = idx >> 6, j = idx & 63;
            at[i * LDAT + j] = g_attn[(((size_t)hv * NCH + n) * CH + i) * CH + j];
        }
        __syncthreads();

        ull vnp[8], ocp[8];
#pragma unroll
        for (int r = 0; r < 8; r++) { vnp[r] = 0ull; ocp[r] = 0ull; }
        for (int dk = 0; dk < 128; dk += 4) {
            float s0 = S[(dk + 0) * LDS33 + vloc];
            float s1 = S[(dk + 1) * LDS33 + vloc];
            float s2 = S[(dk + 2) * LDS33 + vloc];
            float s3 = S[(dk + 3) * LDS33 + vloc];
            ull b0 = pk2(s0, s1), b1 = pk2(s2, s3);
#pragma unroll
            for (int r = 0; r < 8; r++) {
                ulonglong2 w2 = *(ulonglong2*)&ws [(c0 + r) * LDA + dk];
                ulonglong2 q2 = *(ulonglong2*)&qgs[(c0 + r) * LDA + dk];
                fma2(vnp[r], w2.x, b0); fma2(vnp[r], w2.y, b1);
                fma2(ocp[r], q2.x, b0); fma2(ocp[r], q2.y, b1);
            }
        }
#pragma unroll
        for (int r = 0; r < 8; r++) {
            float2 p = upk2(vnp[r]);
            vns[(c0 + r) * LDS33 + vloc] = us[(c0 + r) * LDS33 + vloc] - p.x - p.y;
        }
        __syncthreads();

        for (int j = 0; j < 64; j += 4) {
            ull b0 = pk2(vns[(j + 0) * LDS33 + vloc], vns[(j + 1) * LDS33 + vloc]);
            ull b1 = pk2(vns[(j + 2) * LDS33 + vloc], vns[(j + 3) * LDS33 + vloc]);
#pragma unroll
            for (int r = 0; r < 8; r++) {
                ulonglong2 a2 = *(ulonglong2*)&at[(c0 + r) * LDAT + j];
                fma2(ocp[r], a2.x, b0); fma2(ocp[r], a2.y, b1);
            }
        }
#pragma unroll
        for (int r = 0; r < 8; r++) {
            float2 p = upk2(ocp[r]);
            g_o[(size_t)(n * CH + c0 + r) * 4096 + hv * 128 + v0 + vloc] = p.x + p.y;
        }
        __syncthreads();

        float egl = expf(g_glast[hv * NCH + n]);
        ull eglp = pk2(egl, egl);
        ull sp[8];
#pragma unroll
        for (int p = 0; p < 8; p++) {
            sp[p] = mul2(pk2(S[(dk0 + 2 * p) * LDS33 + vloc], S[(dk0 + 2 * p + 1) * LDS33 + vloc]), eglp);
        }
        for (int c = 0; c < 64; c++) {
            float vc = vns[c * LDS33 + vloc];
            ull bv = pk2(vc, vc);
            ulonglong2 kA = *(ulonglong2*)&kds[c * LDA + dk0];
            ulonglong2 kB = *(ulonglong2*)&kds[c * LDA + dk0 + 4];
            ulonglong2 kC = *(ulonglong2*)&kds[c * LDA + dk0 + 8];
            ulonglong2 kD = *(ulonglong2*)&kds[c * LDA + dk0 + 12];
            fma2(sp[0], kA.x, bv); fma2(sp[1], kA.y, bv);
            fma2(sp[2], kB.x, bv); fma2(sp[3], kB.y, bv);
            fma2(sp[4], kC.x, bv); fma2(sp[5], kC.y, bv);
            fma2(sp[6], kD.x, bv); fma2(sp[7], kD.y, bv);
        }
#pragma unroll
        for (int p = 0; p < 8; p++) {
            float2 v = upk2(sp[p]);
            S[(dk0 + 2 * p) * LDS33 + vloc]     = v.x;
            S[(dk0 + 2 * p + 1) * LDS33 + vloc] = v.y;
        }
        __syncthreads();
    }
}

// ================= gate (silu) + RMS norm → fp16 (warp-per-row) =================
__global__ void gate_rms_kernel(const float* __restrict__ norm_w) {
    int t = blockIdx.x;
    int w = threadIdx.x >> 5;
    int hv = blockIdx.y * 8 + w;
    int lane = threadIdx.x & 31;
    int d0 = lane * 4;

    size_t obase = (size_t)t * 4096 + hv * 128 + d0;
    float4 o4 = *(const float4*)&g_o[obase];
    float4 z4 = *(const float4*)&g_qkvz[(size_t)t * NQ + (hv >> 1) * 768 + 512 + (hv & 1) * 128 + d0];

    float v0 = o4.x * (z4.x / (1.f + __expf(-z4.x)));
    float v1 = o4.y * (z4.y / (1.f + __expf(-z4.y)));
    float v2 = o4.z * (z4.z / (1.f + __expf(-z4.z)));
    float v3 = o4.w * (z4.w / (1.f + __expf(-z4.w)));

    float ss = v0 * v0 + v1 * v1 + v2 * v2 + v3 * v3;
#pragma unroll
    for (int off = 16; off; off >>= 1) ss += __shfl_xor_sync(0xffffffffu, ss, off);
    float r = rsqrtf(ss * (1.f / 128.f) + 1e-6f);

    float4 nw = *(const float4*)&norm_w[d0];
    __half2 p0 = __floats2half2_rn(v0 * r * nw.x, v1 * r * nw.y);
    __half2 p1 = __floats2half2_rn(v2 * r * nw.z, v3 * r * nw.w);
    *(__half2*)&g_ogf[obase]     = p0;
    *(__half2*)&g_ogf[obase + 2] = p1;
}

// ================= launch =================
extern "C" void kernel_launch(void* const* d_in, const int* in_sizes, int n_in,
                              void* d_out, int out_size) {
    const float* x       = (const float*)d_in[0];
    const float* W_qkvz  = (const float*)d_in[3];
    const float* W_ba    = (const float*)d_in[4];
    const float* conv_w  = (const float*)d_in[5];
    const float* dt_bias = (const float*)d_in[6];
    const float* A_log   = (const float*)d_in[7];
    const float* norm_w  = (const float*)d_in[8];
    const float* W_out   = (const float*)d_in[9];
    float* out = (float*)d_out;

    void *p_qkvz = nullptr, *p_xf, *p_wqh, *p_wql, *p_woh, *p_wol, *p_ogf;
    cudaGetSymbolAddress(&p_qkvz, g_qkvz);
    cudaGetSymbolAddress(&p_xf, g_xf);
    cudaGetSymbolAddress(&p_wqh, g_wqh); cudaGetSymbolAddress(&p_wql, g_wql);
    cudaGetSymbolAddress(&p_woh, g_woh); cudaGetSymbolAddress(&p_wol, g_wol);
    cudaGetSymbolAddress(&p_ogf, g_ogf);

    cudaFuncSetAttribute(hgemm2,       cudaFuncAttributeMaxDynamicSharedMemorySize, HG_SMEM);
    cudaFuncSetAttribute(passA_kernel, cudaFuncAttributeMaxDynamicSharedMemorySize, PA_SMEM);
    cudaFuncSetAttribute(scan_kernel,  cudaFuncAttributeMaxDynamicSharedMemorySize, SC_SMEM);

    conv_fp16_kernel<<<(TT * 2048) / 256, 256>>>(x, (__half*)p_xf);
    tsplit_kernel<<<dim3(NQ / 32, 2048 / 32), dim3(32, 8)>>>(W_qkvz, (__half*)p_wqh, (__half*)p_wql, 2048, NQ);
    tsplit_kernel<<<dim3(2048 / 32, 4096 / 32), dim3(32, 8)>>>(W_out, (__half*)p_woh, (__half*)p_wol, 4096, 2048);

    hgemm2<<<dim3(NQ / 256, TT / 128), 512, HG_SMEM>>>(
        (const __half*)p_xf, (const __half*)p_wqh, (const __half*)p_wql,
        (float*)p_qkvz, TT, NQ, 2048);

    gemm_ba<<<256, 256>>>(x, W_ba);
    conv_kernel<<<(CONVD * TT) / 1024, 256>>>(conv_w);
    gbeta_kernel<<<dim3(NCH, HVN), 64>>>(dt_bias, A_log);
    passA_kernel<<<dim3(NCH, HVN), 256, PA_SMEM>>>();
    scan_kernel<<<128, 256, SC_SMEM>>>();
    gate_rms_kernel<<<dim3(TT, HVN / 8), 256>>>(norm_w);

    hgemm2<<<dim3(2048 / 256, TT / 128), 512, HG_SMEM>>>(
        (const __half*)p_ogf, (const __half*)p_woh, (const __half*)p_wol,
        out, TT, 2048, 4096);
}

// round 15
// speedup vs baseline: 1.2093x; 1.2093x over previous
#include <cuda_runtime.h>
#include <cuda_bf16.h>
#include <cuda_fp16.h>
#include <cstdint>

typedef unsigned long long ull;

// ================= constants =================
#define TT    4096
#define NQ    12288
#define CONVD 8192
#define CH    64
#define NCH   64
#define HVN   32
#define LDA   132
#define LDT   65
#define LDS33 33
#define LDAT  68

// ================= device scratch =================
__device__ float g_qkvz[(size_t)TT * NQ];
__device__ float g_ba[TT * 64];
__device__ float g_y[(size_t)CONVD * TT];
__device__ float g_beta[HVN * TT];
__device__ float g_gc[HVN * TT];
__device__ float g_glast[HVN * NCH];
__device__ float g_u [(size_t)HVN * TT * 128];
__device__ float g_w [(size_t)HVN * TT * 128];
__device__ float g_qg[(size_t)HVN * TT * 128];
__device__ float g_kd[(size_t)HVN * TT * 128];
__device__ float g_attn[(size_t)HVN * NCH * CH * CH];
__device__ float g_o [(size_t)TT * 4096];
// fp16 operands (single-precision fp16 GEMMs)
__device__ __half g_xf [(size_t)TT * 2048];
__device__ __half g_wqf[(size_t)NQ * 2048];     // W_qkvz^T
__device__ __half g_wof[(size_t)2048 * 4096];   // W_out^T
__device__ __half g_ogf[(size_t)TT * 4096];

// ================= PTX helpers =================
__device__ __forceinline__ uint32_t s2u(const void* p) {
    uint32_t a;
    asm("{ .reg .u64 t; cvta.to.shared.u64 t, %1; cvt.u32.u64 %0, t; }" : "=r"(a) : "l"(p));
    return a;
}
__device__ __forceinline__ void cpa16(uint32_t d, const void* s) {
    asm volatile("cp.async.cg.shared.global [%0], [%1], 16;" :: "r"(d), "l"(s) : "memory");
}
#define CPA_COMMIT() asm volatile("cp.async.commit_group;" ::: "memory")
__device__ __forceinline__ void ldm_x4(uint32_t* r, uint32_t a) {
    asm volatile("ldmatrix.sync.aligned.m8n8.x4.shared.b16 {%0,%1,%2,%3}, [%4];"
                 : "=r"(r[0]), "=r"(r[1]), "=r"(r[2]), "=r"(r[3]) : "r"(a));
}
__device__ __forceinline__ void mma16816h(float* d, const uint32_t* a, const uint32_t* b) {
    asm volatile("mma.sync.aligned.m16n8k16.row.col.f32.f16.f16.f32 "
                 "{%0,%1,%2,%3}, {%4,%5,%6,%7}, {%8,%9}, {%0,%1,%2,%3};"
                 : "+f"(d[0]), "+f"(d[1]), "+f"(d[2]), "+f"(d[3])
                 : "r"(a[0]), "r"(a[1]), "r"(a[2]), "r"(a[3]), "r"(b[0]), "r"(b[1]));
}
__device__ __forceinline__ ull pk2(float lo, float hi) {
    ull r;
    asm("mov.b64 %0, {%1, %2};" : "=l"(r) : "f"(lo), "f"(hi));
    return r;
}
__device__ __forceinline__ float2 upk2(ull v) {
    float2 r;
    asm("mov.b64 {%0, %1}, %2;" : "=f"(r.x), "=f"(r.y) : "l"(v));
    return r;
}
__device__ __forceinline__ void fma2(ull &d, ull a, ull b) {
    asm("fma.rn.f32x2 %0, %1, %2, %0;" : "+l"(d) : "l"(a), "l"(b));
}
__device__ __forceinline__ ull mul2(ull a, ull b) {
    ull r;
    asm("mul.rn.f32x2 %0, %1, %2;" : "=l"(r) : "l"(a), "l"(b));
    return r;
}

// ================= hgemm1: C[M,N] = A[M,K] @ Bt[N,K]^T  (single fp16, R11 pipeline) =================
// CTA 128x256, 512 thr, BK=32, 3-stage. smem/stage: A[128][40] + B[256][40]
#define HG_STRIDE 40
#define HG_A_EL   (128 * HG_STRIDE)          // 5120
#define HG_B_EL   (256 * HG_STRIDE)          // 10240
#define HG_OFF_B  (HG_A_EL * 2)              // 10240 B
#define HG_STAGE_BYTES (HG_OFF_B + HG_B_EL * 2)  // 30720
#define HG_SMEM (3 * HG_STAGE_BYTES)         // 92160

__device__ __forceinline__ void hg_stage_load(uint32_t sb,
                                              const __half* __restrict__ Af,
                                              const __half* __restrict__ Bf,
                                              int m0, int n0, int K, int k0, int tid) {
    // A: 128 rows x 32 k = 512 16B-tasks
    {
        int r = tid >> 2, q = (tid & 3) * 8;
        uint32_t so = (uint32_t)(r * HG_STRIDE + q) * 2;
        cpa16(sb + so, Af + (size_t)(m0 + r) * K + k0 + q);
    }
    // B: 256 rows x 32 k = 1024 tasks
#pragma unroll
    for (int i = 0; i < 2; i++) {
        int idx = tid + i * 512;
        int r = idx >> 2, q = (idx & 3) * 8;
        uint32_t so = (uint32_t)(r * HG_STRIDE + q) * 2;
        cpa16(sb + HG_OFF_B + so, Bf + (size_t)(n0 + r) * K + k0 + q);
    }
    CPA_COMMIT();
}

__global__ void __launch_bounds__(512, 1) hgemm1(const __half* __restrict__ Af,
                                                 const __half* __restrict__ Bf,
                                                 float* __restrict__ C,
                                                 int M, int N, int K) {
    extern __shared__ __align__(16) char hsm[];
    uint32_t sbase = s2u(hsm);
    int tid = threadIdx.x, lane = tid & 31, wid = tid >> 5;
    int wm = wid >> 3, wn = wid & 7;          // 2 x 8 warps, warp tile 64 x 32
    int m0 = blockIdx.y * 128, n0 = blockIdx.x * 256;

    float acc[4][4][4];
#pragma unroll
    for (int a = 0; a < 4; a++)
#pragma unroll
        for (int b = 0; b < 4; b++)
#pragma unroll
            for (int c = 0; c < 4; c++) acc[a][b][c] = 0.f;

    int NCC = K >> 5;
    hg_stage_load(sbase,                  Af, Bf, m0, n0, K, 0,  tid);
    hg_stage_load(sbase + HG_STAGE_BYTES, Af, Bf, m0, n0, K, 32, tid);

    int arow = wm * 64 + (lane & 15);
    int acol = (lane >> 4) << 3;
    int brow = wn * 32 + (lane & 7) + ((lane >> 4) << 3);
    int bcol = ((lane >> 3) & 1) << 3;

    for (int c = 0; c < NCC; c++) {
        if (c + 1 < NCC) {
            asm volatile("cp.async.wait_group 1;" ::: "memory");
        } else {
            asm volatile("cp.async.wait_group 0;" ::: "memory");
        }
        __syncthreads();

        uint32_t sb = sbase + (c % 3) * HG_STAGE_BYTES;
#pragma unroll
        for (int kc = 0; kc < 32; kc += 16) {
            uint32_t af[4][4], bf[4][2];
#pragma unroll
            for (int mt = 0; mt < 4; mt++) {
                uint32_t ad = sb + (uint32_t)((arow + mt * 16) * HG_STRIDE + kc + acol) * 2;
                ldm_x4(af[mt], ad);
            }
#pragma unroll
            for (int j = 0; j < 2; j++) {
                uint32_t bd = sb + HG_OFF_B + (uint32_t)((brow + j * 16) * HG_STRIDE + kc + bcol) * 2;
                ldm_x4(&bf[2 * j][0], bd);
            }
#pragma unroll
            for (int mt = 0; mt < 4; mt++)
#pragma unroll
                for (int nt = 0; nt < 4; nt++) mma16816h(acc[mt][nt], af[mt], bf[nt]);
        }

        if (c + 2 < NCC)
            hg_stage_load(sbase + ((c + 2) % 3) * HG_STAGE_BYTES, Af, Bf,
                          m0, n0, K, (c + 2) << 5, tid);
    }

#pragma unroll
    for (int mt = 0; mt < 4; mt++)
#pragma unroll
        for (int nt = 0; nt < 4; nt++) {
            int row = m0 + wm * 64 + mt * 16 + (lane >> 2);
            int col = n0 + wn * 32 + nt * 8 + (lane & 3) * 2;
            *(float2*)&C[(size_t)row * N + col]       = make_float2(acc[mt][nt][0], acc[mt][nt][1]);
            *(float2*)&C[(size_t)(row + 8) * N + col] = make_float2(acc[mt][nt][2], acc[mt][nt][3]);
        }
}

// ================= convert / transpose =================
__global__ void conv_fp16_kernel(const float* __restrict__ src, __half* __restrict__ dst) {
    size_t i = (size_t)blockIdx.x * 256 + threadIdx.x;
    dst[i] = __float2half(src[i]);
}

__global__ void tconv_kernel(const float* __restrict__ W, __half* __restrict__ Tf,
                             int R, int Ccols) {
    __shared__ float t[32][33];
    int c0 = blockIdx.x * 32, rr0 = blockIdx.y * 32;
    int tx = threadIdx.x;
    for (int j = threadIdx.y; j < 32; j += 8)
        t[j][tx] = W[(size_t)(rr0 + j) * Ccols + c0 + tx];
    __syncthreads();
    for (int j = threadIdx.y; j < 32; j += 8)
        Tf[(size_t)(c0 + j) * R + rr0 + tx] = __float2half(t[tx][j]);
}

// ================= ba = x @ W_ba =================
__global__ void __launch_bounds__(256) gemm_ba(const float* __restrict__ x, const float* __restrict__ W) {
    __shared__ float xs[16][33];
    __shared__ float Ws[32][65];
    int t0 = blockIdx.x * 16;
    int tid = threadIdx.x;
    int cb = tid & 63;
    int rg = tid >> 6;
    float acc[4] = {0.f, 0.f, 0.f, 0.f};

    for (int k0 = 0; k0 < 2048; k0 += 32) {
        for (int idx = tid; idx < 512; idx += 256) {
            int r = idx >> 5, k = idx & 31;
            xs[r][k] = x[(size_t)(t0 + r) * 2048 + k0 + k];
        }
        for (int idx = tid; idx < 2048; idx += 256) {
            int k = idx >> 6, j = idx & 63;
            Ws[k][j] = W[(size_t)(k0 + k) * 64 + j];
        }
        __syncthreads();
#pragma unroll 8
        for (int k = 0; k < 32; k++) {
            float wv = Ws[k][cb];
#pragma unroll
            for (int r = 0; r < 4; r++)
                acc[r] += xs[rg * 4 + r][k] * wv;
        }
        __syncthreads();
    }
#pragma unroll
    for (int r = 0; r < 4; r++)
        g_ba[(t0 + rg * 4 + r) * 64 + cb] = acc[r];
}

// ================= causal depthwise conv + SiLU (4 outputs/thread) =================
__global__ void conv_kernel(const float* __restrict__ conv_w) {
    int base = (blockIdx.x * 256 + threadIdx.x) * 4;
    int j = base >> 12;
    int p = base & 4095;
    float w0 = conv_w[j * 4 + 0];
    float w1 = conv_w[j * 4 + 1];
    float w2 = conv_w[j * 4 + 2];
    float w3 = conv_w[j * 4 + 3];
    float in[7];
#pragma unroll
    for (int m = 0; m < 7; m++) {
        int pos = p - 3 + m;
        if (pos >= 0) {
            int s = base - 3 + m;
            int h = s >> 21;
            int t = (s >> 9) & 4095;
            int c = s & 511;
            in[m] = g_qkvz[(size_t)t * NQ + h * 768 + c];
        } else in[m] = 0.f;
    }
    float4 out;
    float* po = &out.x;
#pragma unroll
    for (int o = 0; o < 4; o++) {
        float a = w0 * in[o] + w1 * in[o + 1] + w2 * in[o + 2] + w3 * in[o + 3];
        po[o] = a / (1.f + __expf(-a));
    }
    *(float4*)&g_y[base] = out;
}

// ================= beta, g, within-chunk cumsum =================
__global__ void gbeta_kernel(const float* __restrict__ dt_bias, const float* __restrict__ A_log) {
    int n = blockIdx.x, hv = blockIdx.y;
    int i = threadIdx.x;
    int t = n * CH + i;
    int h16 = hv >> 1, r = hv & 1;
    float b = g_ba[t * 64 + h16 * 4 + r];
    float a = g_ba[t * 64 + h16 * 4 + 2 + r];
    float beta = 1.f / (1.f + expf(-b));
    float xx = a + dt_bias[hv];
    float sp = (xx > 20.f) ? xx : log1pf(expf(xx));
    float g = -expf(A_log[hv]) * sp;
    __shared__ float s[64];
    s[i] = g;
    __syncthreads();
#pragma unroll
    for (int off = 1; off < 64; off <<= 1) {
        float v = (i >= off) ? s[i - off] : 0.f;
        __syncthreads();
        s[i] += v;
        __syncthreads();
    }
    g_beta[hv * TT + t] = beta;
    g_gc[hv * TT + t]   = s[i];
    if (i == 63) g_glast[hv * NCH + n] = s[63];
}

// ================= Pass A (R13) =================
#define PA_SMEM ((3*64*LDA + 3*64) * 4)
__global__ void __launch_bounds__(256, 2) passA_kernel() {
    extern __shared__ float sm[];
    float* qs  = sm;
    float* ks  = qs + 64 * LDA;
    float* vs  = ks + 64 * LDA;
    float* gcs = vs + 64 * LDA;
    float* bes = gcs + 64;
    float* wcf = bes + 64;
    float* Mm  = qs;
    float* Ti  = qs + 64 * LDT;

    int n = blockIdx.x, hv = blockIdx.y, h16 = hv >> 1;
    int tid = threadIdx.x;
    int tb = n * CH;

    for (int idx = tid; idx < 8192; idx += 256) {
        int d = idx >> 6, i = idx & 63;
        int t = tb + i;
        qs[i * LDA + d] = g_y[(size_t)(h16 * 128 + d) * TT + t];
        ks[i * LDA + d] = g_y[(size_t)(2048 + h16 * 128 + d) * TT + t];
        vs[i * LDA + d] = g_y[(size_t)(4096 + hv * 128 + d) * TT + t];
    }
    if (tid < 64) {
        gcs[tid] = g_gc[hv * TT + tb + tid];
        bes[tid] = g_beta[hv * TT + tb + tid];
    }
    __syncthreads();
    {
        int row = tid >> 2;
        int d0 = (tid & 3) * 32;
        if (tid < 64) wcf[tid] = bes[tid] * expf(gcs[tid]);
        float sq = 0.f, sk = 0.f;
        for (int d = d0; d < d0 + 32; d += 4) {
            float4 a4 = *(float4*)&qs[row * LDA + d];
            float4 b4 = *(float4*)&ks[row * LDA + d];
            sq += a4.x * a4.x + a4.y * a4.y + a4.z * a4.z + a4.w * a4.w;
            sk += b4.x * b4.x + b4.y * b4.y + b4.z * b4.z + b4.w * b4.w;
        }
        sq += __shfl_xor_sync(0xffffffffu, sq, 1);
        sq += __shfl_xor_sync(0xffffffffu, sq, 2);
        sk += __shfl_xor_sync(0xffffffffu, sk, 1);
        sk += __shfl_xor_sync(0xffffffffu, sk, 2);
        float rq = rsqrtf(sq + 1e-6f) * 0.08838834764831845f;
        float rk = rsqrtf(sk + 1e-6f);
        for (int d = d0; d < d0 + 32; d += 4) {
            float4 a4 = *(float4*)&qs[row * LDA + d];
            float4 b4 = *(float4*)&ks[row * LDA + d];
            a4.x *= rq; a4.y *= rq; a4.z *= rq; a4.w *= rq;
            b4.x *= rk; b4.y *= rk; b4.z *= rk; b4.w *= rk;
            *(float4*)&qs[row * LDA + d] = a4;
            *(float4*)&ks[row * LDA + d] = b4;
        }
    }
    __syncthreads();

    int ti0 = (tid >> 4) * 4;
    int jb  = tid & 15;
    float accK[4][4], accQ[4][4];
    {
        ull aKp[4][4], aQp[4][4];
#pragma unroll
        for (int r = 0; r < 4; r++)
#pragma unroll
            for (int c = 0; c < 4; c++) { aKp[r][c] = 0ull; aQp[r][c] = 0ull; }
        for (int d = 0; d < 128; d += 4) {
            ulonglong2 kj[4], ki[4], qi[4];
#pragma unroll
            for (int c = 0; c < 4; c++) kj[c] = *(ulonglong2*)&ks[(jb + 16 * c) * LDA + d];
#pragma unroll
            for (int r = 0; r < 4; r++) {
                ki[r] = *(ulonglong2*)&ks[(ti0 + r) * LDA + d];
                qi[r] = *(ulonglong2*)&qs[(ti0 + r) * LDA + d];
            }
#pragma unroll
            for (int r = 0; r < 4; r++)
#pragma unroll
                for (int c = 0; c < 4; c++) {
                    fma2(aKp[r][c], ki[r].x, kj[c].x);
                    fma2(aKp[r][c], ki[r].y, kj[c].y);
                    fma2(aQp[r][c], qi[r].x, kj[c].x);
                    fma2(aQp[r][c], qi[r].y, kj[c].y);
                }
        }
#pragma unroll
        for (int r = 0; r < 4; r++)
#pragma unroll
            for (int c = 0; c < 4; c++) {
                float2 pk = upk2(aKp[r][c]); accK[r][c] = pk.x + pk.y;
                float2 pq = upk2(aQp[r][c]); accQ[r][c] = pq.x + pq.y;
            }
#pragma unroll
        for (int r = 0; r < 4; r++)
#pragma unroll
            for (int c = 0; c < 4; c++) {
                int i = ti0 + r, j = jb + 16 * c;
                float dec = (i >= j) ? expf(gcs[i] - gcs[j]) : 0.f;
                g_attn[(((size_t)hv * NCH + n) * CH + i) * CH + j] = (i >= j) ? dec * accQ[r][c] : 0.f;
            }
    }

    float gl = gcs[63];
    for (int idx = tid; idx < 8192; idx += 256) {
        int i = idx >> 7, d = idx & 127;
        size_t ro = ((size_t)hv * TT + tb + i) * 128 + d;
        g_qg[ro] = qs[i * LDA + d] * expf(gcs[i]);
        g_kd[ro] = ks[i * LDA + d] * expf(gl - gcs[i]);
    }
    __syncthreads();

#pragma unroll
    for (int r = 0; r < 4; r++)
#pragma unroll
        for (int c = 0; c < 4; c++) {
            int i = ti0 + r, j = jb + 16 * c;
            float dec = (i > j) ? expf(gcs[i] - gcs[j]) : 0.f;
            Mm[i * LDT + j] = (i > j) ? bes[i] * dec * accK[r][c] : 0.f;
        }
    __syncthreads();

    if (tid < 64) {
        int j = tid;
        for (int i = 0; i < 64; i++) Ti[i * LDT + j] = (i == j) ? 1.f : 0.f;
        for (int i = j + 1; i < 64; i++) {
            float s = 0.f;
            for (int l = j; l < i; l++) s += Mm[i * LDT + l] * Ti[l * LDT + j];
            Ti[i * LDT + j] = -s;
        }
    }
    __syncthreads();

    {
        int i = tid >> 2, d0 = (tid & 3) * 32;
        ull up[16], wp[16];
#pragma unroll
        for (int p = 0; p < 16; p++) { up[p] = 0ull; wp[p] = 0ull; }
        for (int j = 0; j <= i; j++) {
            float tij = Ti[i * LDT + j];
            ull cup = pk2(tij * bes[j], tij * bes[j]);
            ull cwp = pk2(tij * wcf[j], tij * wcf[j]);
#pragma unroll
            for (int q = 0; q < 4; q++) {
                ulonglong2 v2 = *(ulonglong2*)&vs[j * LDA + d0 + q * 4];
                ulonglong2 k2 = *(ulonglong2*)&ks[j * LDA + d0 + q * 4];
                fma2(up[q * 4 + 0], v2.x, cup); fma2(up[q * 4 + 1], v2.y, cup);
                fma2(wp[q * 4 + 0], k2.x, cwp); fma2(wp[q * 4 + 1], k2.y, cwp);
            }
#pragma unroll
            for (int q = 0; q < 4; q++) {
                ulonglong2 v2 = *(ulonglong2*)&vs[j * LDA + d0 + 16 + q * 4];
                ulonglong2 k2 = *(ulonglong2*)&ks[j * LDA + d0 + 16 + q * 4];
                fma2(up[q * 4 + 2], v2.x, cup); fma2(up[q * 4 + 3], v2.y, cup);
                fma2(wp[q * 4 + 2], k2.x, cwp); fma2(wp[q * 4 + 3], k2.y, cwp);
            }
        }
        size_t ro = ((size_t)hv * TT + tb + i) * 128 + d0;
#pragma unroll
        for (int q = 0; q < 4; q++) {
            float2 a0 = upk2(up[q * 4 + 0]), a1 = upk2(up[q * 4 + 1]);
            float2 b0 = upk2(wp[q * 4 + 0]), b1 = upk2(wp[q * 4 + 1]);
            *(float4*)&g_u[ro + q * 4]      = make_float4(a0.x, a0.y, a1.x, a1.y);
            *(float4*)&g_w[ro + q * 4]      = make_float4(b0.x, b0.y, b1.x, b1.y);
            float2 a2 = upk2(up[q * 4 + 2]), a3 = upk2(up[q * 4 + 3]);
            float2 b2 = upk2(wp[q * 4 + 2]), b3 = upk2(wp[q * 4 + 3]);
            *(float4*)&g_u[ro + 16 + q * 4] = make_float4(a2.x, a2.y, a3.x, a3.y);
            *(float4*)&g_w[ro + 16 + q * 4] = make_float4(b2.x, b2.y, b3.x, b3.y);
        }
    }
}

// ================= Scan (R8 proven) =================
#define SC_SMEM ((128*LDS33 + 3*64*LDA + 2*64*LDS33 + 64*LDAT) * 4)
__global__ void __launch_bounds__(256) scan_kernel() {
    extern __shared__ float sm[];
    float* S   = sm;
    float* ws  = S   + 128 * LDS33;
    float* kds = ws  + 64 * LDA;
    float* qgs = kds + 64 * LDA;
    float* us  = qgs + 64 * LDA;
    float* vns = us  + 64 * LDS33;
    float* at  = vns + 64 * LDS33;

    int hv = blockIdx.x >> 2;
    int v0 = (blockIdx.x & 3) * 32;
    int tid = threadIdx.x;
    int vloc = tid & 31;
    int c0 = (tid >> 5) * 8;
    int dk0 = (tid >> 5) * 16;

    for (int idx = tid; idx < 128 * LDS33; idx += 256) S[idx] = 0.f;
    __syncthreads();

    for (int n = 0; n < NCH; n++) {
        size_t base = ((size_t)hv * TT + n * CH) * 128;
        for (int idx4 = tid; idx4 < 2048; idx4 += 256) {
            int i = idx4 >> 5, d4 = (idx4 & 31) * 4;
            *(float4*)&ws [i * LDA + d4] = *(const float4*)&g_w [base + i * 128 + d4];
            *(float4*)&kds[i * LDA + d4] = *(const float4*)&g_kd[base + i * 128 + d4];
            *(float4*)&qgs[i * LDA + d4] = *(const float4*)&g_qg[base + i * 128 + d4];
        }
        for (int idx = tid; idx < 2048; idx += 256) {
            int i = idx >> 5, v = idx & 31;
            us[i * LDS33 + v] = g_u[base + i * 128 + v0 + v];
        }
        for (int idx = tid; idx < 4096; idx += 256) {
            int i = idx >> 6, j = idx & 63;
            at[i * LDAT + j] = g_attn[(((size_t)hv * NCH + n) * CH + i) * CH + j];
        }
        __syncthreads();

        ull vnp[8], ocp[8];
#pragma unroll
        for (int r = 0; r < 8; r++) { vnp[r] = 0ull; ocp[r] = 0ull; }
        for (int dk = 0; dk < 128; dk += 4) {
            float s0 = S[(dk + 0) * LDS33 + vloc];
            float s1 = S[(dk + 1) * LDS33 + vloc];
            float s2 = S[(dk + 2) * LDS33 + vloc];
            float s3 = S[(dk + 3) * LDS33 + vloc];
            ull b0 = pk2(s0, s1), b1 = pk2(s2, s3);
#pragma unroll
            for (int r = 0; r < 8; r++) {
                ulonglong2 w2 = *(ulonglong2*)&ws [(c0 + r) * LDA + dk];
                ulonglong2 q2 = *(ulonglong2*)&qgs[(c0 + r) * LDA + dk];
                fma2(vnp[r], w2.x, b0); fma2(vnp[r], w2.y, b1);
                fma2(ocp[r], q2.x, b0); fma2(ocp[r], q2.y, b1);
            }
        }
#pragma unroll
        for (int r = 0; r < 8; r++) {
            float2 p = upk2(vnp[r]);
            vns[(c0 + r) * LDS33 + vloc] = us[(c0 + r) * LDS33 + vloc] - p.x - p.y;
        }
        __syncthreads();

        for (int j = 0; j < 64; j += 4) {
            ull b0 = pk2(vns[(j + 0) * LDS33 + vloc], vns[(j + 1) * LDS33 + vloc]);
            ull b1 = pk2(vns[(j + 2) * LDS33 + vloc], vns[(j + 3) * LDS33 + vloc]);
#pragma unroll
            for (int r = 0; r < 8; r++) {
                ulonglong2 a2 = *(ulonglong2*)&at[(c0 + r) * LDAT + j];
                fma2(ocp[r], a2.x, b0); fma2(ocp[r], a2.y, b1);
            }
        }
#pragma unroll
        for (int r = 0; r < 8; r++) {
            float2 p = upk2(ocp[r]);
            g_o[(size_t)(n * CH + c0 + r) * 4096 + hv * 128 + v0 + vloc] = p.x + p.y;
        }
        __syncthreads();

        float egl = expf(g_glast[hv * NCH + n]);
        ull eglp = pk2(egl, egl);
        ull sp[8];
#pragma unroll
        for (int p = 0; p < 8; p++) {
            sp[p] = mul2(pk2(S[(dk0 + 2 * p) * LDS33 + vloc], S[(dk0 + 2 * p + 1) * LDS33 + vloc]), eglp);
        }
        for (int c = 0; c < 64; c++) {
            float vc = vns[c * LDS33 + vloc];
            ull bv = pk2(vc, vc);
            ulonglong2 kA = *(ulonglong2*)&kds[c * LDA + dk0];
            ulonglong2 kB = *(ulonglong2*)&kds[c * LDA + dk0 + 4];
            ulonglong2 kC = *(ulonglong2*)&kds[c * LDA + dk0 + 8];
            ulonglong2 kD = *(ulonglong2*)&kds[c * LDA + dk0 + 12];
            fma2(sp[0], kA.x, bv); fma2(sp[1], kA.y, bv);
            fma2(sp[2], kB.x, bv); fma2(sp[3], kB.y, bv);
            fma2(sp[4], kC.x, bv); fma2(sp[5], kC.y, bv);
            fma2(sp[6], kD.x, bv); fma2(sp[7], kD.y, bv);
        }
#pragma unroll
        for (int p = 0; p < 8; p++) {
            float2 v = upk2(sp[p]);
            S[(dk0 + 2 * p) * LDS33 + vloc]     = v.x;
            S[(dk0 + 2 * p + 1) * LDS33 + vloc] = v.y;
        }
        __syncthreads();
    }
}

// ================= gate (silu) + RMS norm → fp16 (warp-per-row) =================
__global__ void gate_rms_kernel(const float* __restrict__ norm_w) {
    int t = blockIdx.x;
    int w = threadIdx.x >> 5;
    int hv = blockIdx.y * 8 + w;
    int lane = threadIdx.x & 31;
    int d0 = lane * 4;

    size_t obase = (size_t)t * 4096 + hv * 128 + d0;
    float4 o4 = *(const float4*)&g_o[obase];
    float4 z4 = *(const float4*)&g_qkvz[(size_t)t * NQ + (hv >> 1) * 768 + 512 + (hv & 1) * 128 + d0];

    float v0 = o4.x * (z4.x / (1.f + __expf(-z4.x)));
    float v1 = o4.y * (z4.y / (1.f + __expf(-z4.y)));
    float v2 = o4.z * (z4.z / (1.f + __expf(-z4.z)));
    float v3 = o4.w * (z4.w / (1.f + __expf(-z4.w)));

    float ss = v0 * v0 + v1 * v1 + v2 * v2 + v3 * v3;
#pragma unroll
    for (int off = 16; off; off >>= 1) ss += __shfl_xor_sync(0xffffffffu, ss, off);
    float r = rsqrtf(ss * (1.f / 128.f) + 1e-6f);

    float4 nw = *(const float4*)&norm_w[d0];
    __half2 p0 = __floats2half2_rn(v0 * r * nw.x, v1 * r * nw.y);
    __half2 p1 = __floats2half2_rn(v2 * r * nw.z, v3 * r * nw.w);
    *(__half2*)&g_ogf[obase]     = p0;
    *(__half2*)&g_ogf[obase + 2] = p1;
}

// ================= launch =================
extern "C" void kernel_launch(void* const* d_in, const int* in_sizes, int n_in,
                              void* d_out, int out_size) {
    const float* x       = (const float*)d_in[0];
    const float* W_qkvz  = (const float*)d_in[3];
    const float* W_ba    = (const float*)d_in[4];
    const float* conv_w  = (const float*)d_in[5];
    const float* dt_bias = (const float*)d_in[6];
    const float* A_log   = (const float*)d_in[7];
    const float* norm_w  = (const float*)d_in[8];
    const float* W_out   = (const float*)d_in[9];
    float* out = (float*)d_out;

    void *p_qkvz = nullptr, *p_xf, *p_wqf, *p_wof, *p_ogf;
    cudaGetSymbolAddress(&p_qkvz, g_qkvz);
    cudaGetSymbolAddress(&p_xf, g_xf);
    cudaGetSymbolAddress(&p_wqf, g_wqf);
    cudaGetSymbolAddress(&p_wof, g_wof);
    cudaGetSymbolAddress(&p_ogf, g_ogf);

    cudaFuncSetAttribute(hgemm1,       cudaFuncAttributeMaxDynamicSharedMemorySize, HG_SMEM);
    cudaFuncSetAttribute(passA_kernel, cudaFuncAttributeMaxDynamicSharedMemorySize, PA_SMEM);
    cudaFuncSetAttribute(scan_kernel,  cudaFuncAttributeMaxDynamicSharedMemorySize, SC_SMEM);

    conv_fp16_kernel<<<(TT * 2048) / 256, 256>>>(x, (__half*)p_xf);
    tconv_kernel<<<dim3(NQ / 32, 2048 / 32), dim3(32, 8)>>>(W_qkvz, (__half*)p_wqf, 2048, NQ);
    tconv_kernel<<<dim3(2048 / 32, 4096 / 32), dim3(32, 8)>>>(W_out, (__half*)p_wof, 4096, 2048);

    // GEMM1: qkvz = x @ W_qkvz (single fp16)
    hgemm1<<<dim3(NQ / 256, TT / 128), 512, HG_SMEM>>>(
        (const __half*)p_xf, (const __half*)p_wqf, (float*)p_qkvz, TT, NQ, 2048);

    gemm_ba<<<256, 256>>>(x, W_ba);
    conv_kernel<<<(CONVD * TT) / 1024, 256>>>(conv_w);
    gbeta_kernel<<<dim3(NCH, HVN), 64>>>(dt_bias, A_log);
    passA_kernel<<<dim3(NCH, HVN), 256, PA_SMEM>>>();
    scan_kernel<<<128, 256, SC_SMEM>>>();
    gate_rms_kernel<<<dim3(TT, HVN / 8), 256>>>(norm_w);

    // GEMM3: out = og @ W_out (single fp16)
    hgemm1<<<dim3(2048 / 256, TT / 128), 512, HG_SMEM>>>(
        (const __half*)p_ogf, (const __half*)p_wof, out, TT, 2048, 4096);
}

// round 16
// speedup vs baseline: 1.2496x; 1.0333x over previous
#include <cuda_runtime.h>
#include <cuda_bf16.h>
#include <cuda_fp16.h>
#include <cstdint>

typedef unsigned long long ull;

// ================= constants =================
#define TT    4096
#define NQ    12288
#define CONVD 8192
#define CH    64
#define NCH   64
#define HVN   32
#define LDA   132
#define LDT   65
#define LDS33 33
#define LDAT  68

// ================= device scratch =================
__device__ float g_qkvz[(size_t)TT * NQ];
__device__ float g_ba[TT * 64];
__device__ float g_y[(size_t)CONVD * TT];
__device__ float g_beta[HVN * TT];
__device__ float g_gc[HVN * TT];
__device__ float g_glast[HVN * NCH];
__device__ float g_u [(size_t)HVN * TT * 128];
__device__ float g_w [(size_t)HVN * TT * 128];
__device__ float g_qg[(size_t)HVN * TT * 128];
__device__ float g_kd[(size_t)HVN * TT * 128];
__device__ float g_attn[(size_t)HVN * NCH * CH * CH];
__device__ float g_o [(size_t)TT * 4096];
// fp16 operands (single-precision fp16 GEMMs)
__device__ __half g_xf [(size_t)TT * 2048];
__device__ __half g_wqf[(size_t)NQ * 2048];     // W_qkvz^T
__device__ __half g_wof[(size_t)2048 * 4096];   // W_out^T
__device__ __half g_ogf[(size_t)TT * 4096];

// ================= PTX helpers =================
__device__ __forceinline__ uint32_t s2u(const void* p) {
    uint32_t a;
    asm("{ .reg .u64 t; cvta.to.shared.u64 t, %1; cvt.u32.u64 %0, t; }" : "=r"(a) : "l"(p));
    return a;
}
__device__ __forceinline__ void cpa16(uint32_t d, const void* s) {
    asm volatile("cp.async.cg.shared.global [%0], [%1], 16;" :: "r"(d), "l"(s) : "memory");
}
#define CPA_COMMIT() asm volatile("cp.async.commit_group;" ::: "memory")
__device__ __forceinline__ void ldm_x4(uint32_t* r, uint32_t a) {
    asm volatile("ldmatrix.sync.aligned.m8n8.x4.shared.b16 {%0,%1,%2,%3}, [%4];"
                 : "=r"(r[0]), "=r"(r[1]), "=r"(r[2]), "=r"(r[3]) : "r"(a));
}
__device__ __forceinline__ void mma16816h(float* d, const uint32_t* a, const uint32_t* b) {
    asm volatile("mma.sync.aligned.m16n8k16.row.col.f32.f16.f16.f32 "
                 "{%0,%1,%2,%3}, {%4,%5,%6,%7}, {%8,%9}, {%0,%1,%2,%3};"
                 : "+f"(d[0]), "+f"(d[1]), "+f"(d[2]), "+f"(d[3])
                 : "r"(a[0]), "r"(a[1]), "r"(a[2]), "r"(a[3]), "r"(b[0]), "r"(b[1]));
}
__device__ __forceinline__ ull pk2(float lo, float hi) {
    ull r;
    asm("mov.b64 %0, {%1, %2};" : "=l"(r) : "f"(lo), "f"(hi));
    return r;
}
__device__ __forceinline__ float2 upk2(ull v) {
    float2 r;
    asm("mov.b64 {%0, %1}, %2;" : "=f"(r.x), "=f"(r.y) : "l"(v));
    return r;
}
__device__ __forceinline__ void fma2(ull &d, ull a, ull b) {
    asm("fma.rn.f32x2 %0, %1, %2, %0;" : "+l"(d) : "l"(a), "l"(b));
}
__device__ __forceinline__ ull mul2(ull a, ull b) {
    ull r;
    asm("mul.rn.f32x2 %0, %1, %2;" : "=l"(r) : "l"(a), "l"(b));
    return r;
}

// ================= hgemm1 v2: single fp16, CTA 128x256, 512 thr, BK=64, 3-stage (R11 ordering) =================
#define HG_STRIDE 72                          // 64 + 8 pad; ldmatrix conflict-free (16B-bank offset 16*r)
#define HG_A_BYTES (128 * HG_STRIDE * 2)      // 18432
#define HG_B_BYTES (256 * HG_STRIDE * 2)      // 36864
#define HG_OFF_B   HG_A_BYTES                 // 18432
#define HG_STAGE_BYTES (HG_OFF_B + HG_B_BYTES)   // 55296
#define HG_SMEM (3 * HG_STAGE_BYTES)          // 165888

__device__ __forceinline__ void hg_stage_load(uint32_t sb,
                                              const __half* __restrict__ Af,
                                              const __half* __restrict__ Bf,
                                              int m0, int n0, int K, int k0, int tid) {
    // A: 128 rows x 64 k = 1024 16B-tasks → 2 per thread
#pragma unroll
    for (int i = 0; i < 2; i++) {
        int idx = tid + i * 512;
        int r = idx >> 3, q = (idx & 7) * 8;
        uint32_t so = (uint32_t)(r * HG_STRIDE + q) * 2;
        cpa16(sb + so, Af + (size_t)(m0 + r) * K + k0 + q);
    }
    // B: 256 rows x 64 k = 2048 tasks → 4 per thread
#pragma unroll
    for (int i = 0; i < 4; i++) {
        int idx = tid + i * 512;
        int r = idx >> 3, q = (idx & 7) * 8;
        uint32_t so = (uint32_t)(r * HG_STRIDE + q) * 2;
        cpa16(sb + HG_OFF_B + so, Bf + (size_t)(n0 + r) * K + k0 + q);
    }
    CPA_COMMIT();
}

__global__ void __launch_bounds__(512, 1) hgemm1(const __half* __restrict__ Af,
                                                 const __half* __restrict__ Bf,
                                                 float* __restrict__ C,
                                                 int M, int N, int K) {
    extern __shared__ __align__(16) char hsm[];
    uint32_t sbase = s2u(hsm);
    int tid = threadIdx.x, lane = tid & 31, wid = tid >> 5;
    int wm = wid >> 3, wn = wid & 7;          // 2 x 8 warps, warp tile 64 x 32
    int m0 = blockIdx.y * 128, n0 = blockIdx.x * 256;

    float acc[4][4][4];
#pragma unroll
    for (int a = 0; a < 4; a++)
#pragma unroll
        for (int b = 0; b < 4; b++)
#pragma unroll
            for (int c = 0; c < 4; c++) acc[a][b][c] = 0.f;

    int NCC = K >> 6;                         // BK = 64
    hg_stage_load(sbase,                  Af, Bf, m0, n0, K, 0,  tid);
    hg_stage_load(sbase + HG_STAGE_BYTES, Af, Bf, m0, n0, K, 64, tid);

    int arow = wm * 64 + (lane & 15);
    int acol = (lane >> 4) << 3;
    int brow = wn * 32 + (lane & 7) + ((lane >> 4) << 3);
    int bcol = ((lane >> 3) & 1) << 3;

    for (int c = 0; c < NCC; c++) {
        if (c + 1 < NCC) {
            asm volatile("cp.async.wait_group 1;" ::: "memory");   // retires load(c)
        } else {
            asm volatile("cp.async.wait_group 0;" ::: "memory");   // last stage: drain
        }
        __syncthreads();

        uint32_t sb = sbase + (c % 3) * HG_STAGE_BYTES;
#pragma unroll
        for (int kc = 0; kc < 64; kc += 16) {
            uint32_t af[4][4], bf[4][2];
#pragma unroll
            for (int mt = 0; mt < 4; mt++) {
                uint32_t ad = sb + (uint32_t)((arow + mt * 16) * HG_STRIDE + kc + acol) * 2;
                ldm_x4(af[mt], ad);
            }
#pragma unroll
            for (int j = 0; j < 2; j++) {
                uint32_t bd = sb + HG_OFF_B + (uint32_t)((brow + j * 16) * HG_STRIDE + kc + bcol) * 2;
                ldm_x4(&bf[2 * j][0], bd);
            }
#pragma unroll
            for (int mt = 0; mt < 4; mt++)
#pragma unroll
                for (int nt = 0; nt < 4; nt++) mma16816h(acc[mt][nt], af[mt], bf[nt]);
        }

        if (c + 2 < NCC)
            hg_stage_load(sbase + ((c + 2) % 3) * HG_STAGE_BYTES, Af, Bf,
                          m0, n0, K, (c + 2) << 6, tid);
    }

#pragma unroll
    for (int mt = 0; mt < 4; mt++)
#pragma unroll
        for (int nt = 0; nt < 4; nt++) {
            int row = m0 + wm * 64 + mt * 16 + (lane >> 2);
            int col = n0 + wn * 32 + nt * 8 + (lane & 3) * 2;
            *(float2*)&C[(size_t)row * N + col]       = make_float2(acc[mt][nt][0], acc[mt][nt][1]);
            *(float2*)&C[(size_t)(row + 8) * N + col] = make_float2(acc[mt][nt][2], acc[mt][nt][3]);
        }
}

// ================= convert / transpose =================
__global__ void conv_fp16_kernel(const float* __restrict__ src, __half* __restrict__ dst) {
    size_t i = (size_t)blockIdx.x * 256 + threadIdx.x;
    dst[i] = __float2half(src[i]);
}

__global__ void tconv_kernel(const float* __restrict__ W, __half* __restrict__ Tf,
                             int R, int Ccols) {
    __shared__ float t[32][33];
    int c0 = blockIdx.x * 32, rr0 = blockIdx.y * 32;
    int tx = threadIdx.x;
    for (int j = threadIdx.y; j < 32; j += 8)
        t[j][tx] = W[(size_t)(rr0 + j) * Ccols + c0 + tx];
    __syncthreads();
    for (int j = threadIdx.y; j < 32; j += 8)
        Tf[(size_t)(c0 + j) * R + rr0 + tx] = __float2half(t[tx][j]);
}

// ================= ba = x @ W_ba =================
__global__ void __launch_bounds__(256) gemm_ba(const float* __restrict__ x, const float* __restrict__ W) {
    __shared__ float xs[16][33];
    __shared__ float Ws[32][65];
    int t0 = blockIdx.x * 16;
    int tid = threadIdx.x;
    int cb = tid & 63;
    int rg = tid >> 6;
    float acc[4] = {0.f, 0.f, 0.f, 0.f};

    for (int k0 = 0; k0 < 2048; k0 += 32) {
        for (int idx = tid; idx < 512; idx += 256) {
            int r = idx >> 5, k = idx & 31;
            xs[r][k] = x[(size_t)(t0 + r) * 2048 + k0 + k];
        }
        for (int idx = tid; idx < 2048; idx += 256) {
            int k = idx >> 6, j = idx & 63;
            Ws[k][j] = W[(size_t)(k0 + k) * 64 + j];
        }
        __syncthreads();
#pragma unroll 8
        for (int k = 0; k < 32; k++) {
            float wv = Ws[k][cb];
#pragma unroll
            for (int r = 0; r < 4; r++)
                acc[r] += xs[rg * 4 + r][k] * wv;
        }
        __syncthreads();
    }
#pragma unroll
    for (int r = 0; r < 4; r++)
        g_ba[(t0 + rg * 4 + r) * 64 + cb] = acc[r];
}

// ================= causal depthwise conv + SiLU (4 outputs/thread) =================
__global__ void conv_kernel(const float* __restrict__ conv_w) {
    int base = (blockIdx.x * 256 + threadIdx.x) * 4;
    int j = base >> 12;
    int p = base & 4095;
    float w0 = conv_w[j * 4 + 0];
    float w1 = conv_w[j * 4 + 1];
    float w2 = conv_w[j * 4 + 2];
    float w3 = conv_w[j * 4 + 3];
    float in[7];
#pragma unroll
    for (int m = 0; m < 7; m++) {
        int pos = p - 3 + m;
        if (pos >= 0) {
            int s = base - 3 + m;
            int h = s >> 21;
            int t = (s >> 9) & 4095;
            int c = s & 511;
            in[m] = g_qkvz[(size_t)t * NQ + h * 768 + c];
        } else in[m] = 0.f;
    }
    float4 out;
    float* po = &out.x;
#pragma unroll
    for (int o = 0; o < 4; o++) {
        float a = w0 * in[o] + w1 * in[o + 1] + w2 * in[o + 2] + w3 * in[o + 3];
        po[o] = a / (1.f + __expf(-a));
    }
    *(float4*)&g_y[base] = out;
}

// ================= beta, g, within-chunk cumsum =================
__global__ void gbeta_kernel(const float* __restrict__ dt_bias, const float* __restrict__ A_log) {
    int n = blockIdx.x, hv = blockIdx.y;
    int i = threadIdx.x;
    int t = n * CH + i;
    int h16 = hv >> 1, r = hv & 1;
    float b = g_ba[t * 64 + h16 * 4 + r];
    float a = g_ba[t * 64 + h16 * 4 + 2 + r];
    float beta = 1.f / (1.f + expf(-b));
    float xx = a + dt_bias[hv];
    float sp = (xx > 20.f) ? xx : log1pf(expf(xx));
    float g = -expf(A_log[hv]) * sp;
    __shared__ float s[64];
    s[i] = g;
    __syncthreads();
#pragma unroll
    for (int off = 1; off < 64; off <<= 1) {
        float v = (i >= off) ? s[i - off] : 0.f;
        __syncthreads();
        s[i] += v;
        __syncthreads();
    }
    g_beta[hv * TT + t] = beta;
    g_gc[hv * TT + t]   = s[i];
    if (i == 63) g_glast[hv * NCH + n] = s[63];
}

// ================= Pass A (R13/R15) =================
#define PA_SMEM ((3*64*LDA + 3*64) * 4)
__global__ void __launch_bounds__(256, 2) passA_kernel() {
    extern __shared__ float sm[];
    float* qs  = sm;
    float* ks  = qs + 64 * LDA;
    float* vs  = ks + 64 * LDA;
    float* gcs = vs + 64 * LDA;
    float* bes = gcs + 64;
    float* wcf = bes + 64;
    float* Mm  = qs;
    float* Ti  = qs + 64 * LDT;

    int n = blockIdx.x, hv = blockIdx.y, h16 = hv >> 1;
    int tid = threadIdx.x;
    int tb = n * CH;

    for (int idx = tid; idx < 8192; idx += 256) {
        int d = idx >> 6, i = idx & 63;
        int t = tb + i;
        qs[i * LDA + d] = g_y[(size_t)(h16 * 128 + d) * TT + t];
        ks[i * LDA + d] = g_y[(size_t)(2048 + h16 * 128 + d) * TT + t];
        vs[i * LDA + d] = g_y[(size_t)(4096 + hv * 128 + d) * TT + t];
    }
    if (tid < 64) {
        gcs[tid] = g_gc[hv * TT + tb + tid];
        bes[tid] = g_beta[hv * TT + tb + tid];
    }
    __syncthreads();
    {
        int row = tid >> 2;
        int d0 = (tid & 3) * 32;
        if (tid < 64) wcf[tid] = bes[tid] * expf(gcs[tid]);
        float sq = 0.f, sk = 0.f;
        for (int d = d0; d < d0 + 32; d += 4) {
            float4 a4 = *(float4*)&qs[row * LDA + d];
            float4 b4 = *(float4*)&ks[row * LDA + d];
            sq += a4.x * a4.x + a4.y * a4.y + a4.z * a4.z + a4.w * a4.w;
            sk += b4.x * b4.x + b4.y * b4.y + b4.z * b4.z + b4.w * b4.w;
        }
        sq += __shfl_xor_sync(0xffffffffu, sq, 1);
        sq += __shfl_xor_sync(0xffffffffu, sq, 2);
        sk += __shfl_xor_sync(0xffffffffu, sk, 1);
        sk += __shfl_xor_sync(0xffffffffu, sk, 2);
        float rq = rsqrtf(sq + 1e-6f) * 0.08838834764831845f;
        float rk = rsqrtf(sk + 1e-6f);
        for (int d = d0; d < d0 + 32; d += 4) {
            float4 a4 = *(float4*)&qs[row * LDA + d];
            float4 b4 = *(float4*)&ks[row * LDA + d];
            a4.x *= rq; a4.y *= rq; a4.z *= rq; a4.w *= rq;
            b4.x *= rk; b4.y *= rk; b4.z *= rk; b4.w *= rk;
            *(float4*)&qs[row * LDA + d] = a4;
            *(float4*)&ks[row * LDA + d] = b4;
        }
    }
    __syncthreads();

    int ti0 = (tid >> 4) * 4;
    int jb  = tid & 15;
    float accK[4][4], accQ[4][4];
    {
        ull aKp[4][4], aQp[4][4];
#pragma unroll
        for (int r = 0; r < 4; r++)
#pragma unroll
            for (int c = 0; c < 4; c++) { aKp[r][c] = 0ull; aQp[r][c] = 0ull; }
        for (int d = 0; d < 128; d += 4) {
            ulonglong2 kj[4], ki[4], qi[4];
#pragma unroll
            for (int c = 0; c < 4; c++) kj[c] = *(ulonglong2*)&ks[(jb + 16 * c) * LDA + d];
#pragma unroll
            for (int r = 0; r < 4; r++) {
                ki[r] = *(ulonglong2*)&ks[(ti0 + r) * LDA + d];
                qi[r] = *(ulonglong2*)&qs[(ti0 + r) * LDA + d];
            }
#pragma unroll
            for (int r = 0; r < 4; r++)
#pragma unroll
                for (int c = 0; c < 4; c++) {
                    fma2(aKp[r][c], ki[r].x, kj[c].x);
                    fma2(aKp[r][c], ki[r].y, kj[c].y);
                    fma2(aQp[r][c], qi[r].x, kj[c].x);
                    fma2(aQp[r][c], qi[r].y, kj[c].y);
                }
        }
#pragma unroll
        for (int r = 0; r < 4; r++)
#pragma unroll
            for (int c = 0; c < 4; c++) {
                float2 pk = upk2(aKp[r][c]); accK[r][c] = pk.x + pk.y;
                float2 pq = upk2(aQp[r][c]); accQ[r][c] = pq.x + pq.y;
            }
#pragma unroll
        for (int r = 0; r < 4; r++)
#pragma unroll
            for (int c = 0; c < 4; c++) {
                int i = ti0 + r, j = jb + 16 * c;
                float dec = (i >= j) ? expf(gcs[i] - gcs[j]) : 0.f;
                g_attn[(((size_t)hv * NCH + n) * CH + i) * CH + j] = (i >= j) ? dec * accQ[r][c] : 0.f;
            }
    }

    float gl = gcs[63];
    for (int idx = tid; idx < 8192; idx += 256) {
        int i = idx >> 7, d = idx & 127;
        size_t ro = ((size_t)hv * TT + tb + i) * 128 + d;
        g_qg[ro] = qs[i * LDA + d] * expf(gcs[i]);
        g_kd[ro] = ks[i * LDA + d] * expf(gl - gcs[i]);
    }
    __syncthreads();

#pragma unroll
    for (int r = 0; r < 4; r++)
#pragma unroll
        for (int c = 0; c < 4; c++) {
            int i = ti0 + r, j = jb + 16 * c;
            float dec = (i > j) ? expf(gcs[i] - gcs[j]) : 0.f;
            Mm[i * LDT + j] = (i > j) ? bes[i] * dec * accK[r][c] : 0.f;
        }
    __syncthreads();

    if (tid < 64) {
        int j = tid;
        for (int i = 0; i < 64; i++) Ti[i * LDT + j] = (i == j) ? 1.f : 0.f;
        for (int i = j + 1; i < 64; i++) {
            float s = 0.f;
            for (int l = j; l < i; l++) s += Mm[i * LDT + l] * Ti[l * LDT + j];
            Ti[i * LDT + j] = -s;
        }
    }
    __syncthreads();

    {
        int i = tid >> 2, d0 = (tid & 3) * 32;
        ull up[16], wp[16];
#pragma unroll
        for (int p = 0; p < 16; p++) { up[p] = 0ull; wp[p] = 0ull; }
        for (int j = 0; j <= i; j++) {
            float tij = Ti[i * LDT + j];
            ull cup = pk2(tij * bes[j], tij * bes[j]);
            ull cwp = pk2(tij * wcf[j], tij * wcf[j]);
#pragma unroll
            for (int q = 0; q < 4; q++) {
                ulonglong2 v2 = *(ulonglong2*)&vs[j * LDA + d0 + q * 4];
                ulonglong2 k2 = *(ulonglong2*)&ks[j * LDA + d0 + q * 4];
                fma2(up[q * 4 + 0], v2.x, cup); fma2(up[q * 4 + 1], v2.y, cup);
                fma2(wp[q * 4 + 0], k2.x, cwp); fma2(wp[q * 4 + 1], k2.y, cwp);
            }
#pragma unroll
            for (int q = 0; q < 4; q++) {
                ulonglong2 v2 = *(ulonglong2*)&vs[j * LDA + d0 + 16 + q * 4];
                ulonglong2 k2 = *(ulonglong2*)&ks[j * LDA + d0 + 16 + q * 4];
                fma2(up[q * 4 + 2], v2.x, cup); fma2(up[q * 4 + 3], v2.y, cup);
                fma2(wp[q * 4 + 2], k2.x, cwp); fma2(wp[q * 4 + 3], k2.y, cwp);
            }
        }
        size_t ro = ((size_t)hv * TT + tb + i) * 128 + d0;
#pragma unroll
        for (int q = 0; q < 4; q++) {
            float2 a0 = upk2(up[q * 4 + 0]), a1 = upk2(up[q * 4 + 1]);
            float2 b0 = upk2(wp[q * 4 + 0]), b1 = upk2(wp[q * 4 + 1]);
            *(float4*)&g_u[ro + q * 4]      = make_float4(a0.x, a0.y, a1.x, a1.y);
            *(float4*)&g_w[ro + q * 4]      = make_float4(b0.x, b0.y, b1.x, b1.y);
            float2 a2 = upk2(up[q * 4 + 2]), a3 = upk2(up[q * 4 + 3]);
            float2 b2 = upk2(wp[q * 4 + 2]), b3 = upk2(wp[q * 4 + 3]);
            *(float4*)&g_u[ro + 16 + q * 4] = make_float4(a2.x, a2.y, a3.x, a3.y);
            *(float4*)&g_w[ro + 16 + q * 4] = make_float4(b2.x, b2.y, b3.x, b3.y);
        }
    }
}

// ================= Scan (R8 + redundant barrier removed) =================
#define SC_SMEM ((128*LDS33 + 3*64*LDA + 2*64*LDS33 + 64*LDAT) * 4)
__global__ void __launch_bounds__(256) scan_kernel() {
    extern __shared__ float sm[];
    float* S   = sm;
    float* ws  = S   + 128 * LDS33;
    float* kds = ws  + 64 * LDA;
    float* qgs = kds + 64 * LDA;
    float* us  = qgs + 64 * LDA;
    float* vns = us  + 64 * LDS33;
    float* at  = vns + 64 * LDS33;

    int hv = blockIdx.x >> 2;
    int v0 = (blockIdx.x & 3) * 32;
    int tid = threadIdx.x;
    int vloc = tid & 31;
    int c0 = (tid >> 5) * 8;
    int dk0 = (tid >> 5) * 16;

    for (int idx = tid; idx < 128 * LDS33; idx += 256) S[idx] = 0.f;
    __syncthreads();

    for (int n = 0; n < NCH; n++) {
        size_t base = ((size_t)hv * TT + n * CH) * 128;
        for (int idx4 = tid; idx4 < 2048; idx4 += 256) {
            int i = idx4 >> 5, d4 = (idx4 & 31) * 4;
            *(float4*)&ws [i * LDA + d4] = *(const float4*)&g_w [base + i * 128 + d4];
            *(float4*)&kds[i * LDA + d4] = *(const float4*)&g_kd[base + i * 128 + d4];
            *(float4*)&qgs[i * LDA + d4] = *(const float4*)&g_qg[base + i * 128 + d4];
        }
        for (int idx = tid; idx < 2048; idx += 256) {
            int i = idx >> 5, v = idx & 31;
            us[i * LDS33 + v] = g_u[base + i * 128 + v0 + v];
        }
        for (int idx = tid; idx < 4096; idx += 256) {
            int i = idx >> 6, j = idx & 63;
            at[i * LDAT + j] = g_attn[(((size_t)hv * NCH + n) * CH + i) * CH + j];
        }
        __syncthreads();

        ull vnp[8], ocp[8];
#pragma unroll
        for (int r = 0; r < 8; r++) { vnp[r] = 0ull; ocp[r] = 0ull; }
        for (int dk = 0; dk < 128; dk += 4) {
            float s0 = S[(dk + 0) * LDS33 + vloc];
            float s1 = S[(dk + 1) * LDS33 + vloc];
            float s2 = S[(dk + 2) * LDS33 + vloc];
            float s3 = S[(dk + 3) * LDS33 + vloc];
            ull b0 = pk2(s0, s1), b1 = pk2(s2, s3);
#pragma unroll
            for (int r = 0; r < 8; r++) {
                ulonglong2 w2 = *(ulonglong2*)&ws [(c0 + r) * LDA + dk];
                ulonglong2 q2 = *(ulonglong2*)&qgs[(c0 + r) * LDA + dk];
                fma2(vnp[r], w2.x, b0); fma2(vnp[r], w2.y, b1);
                fma2(ocp[r], q2.x, b0); fma2(ocp[r], q2.y, b1);
            }
        }
#pragma unroll
        for (int r = 0; r < 8; r++) {
            float2 p = upk2(vnp[r]);
            vns[(c0 + r) * LDS33 + vloc] = us[(c0 + r) * LDS33 + vloc] - p.x - p.y;
        }
        __syncthreads();

        // phase2: oc += attn @ v_new ; phase3 (no barrier needed between them:
        // phase3 writes S rows only this warp-group owns, reads vns/kds already synced)
        for (int j = 0; j < 64; j += 4) {
            ull b0 = pk2(vns[(j + 0) * LDS33 + vloc], vns[(j + 1) * LDS33 + vloc]);
            ull b1 = pk2(vns[(j + 2) * LDS33 + vloc], vns[(j + 3) * LDS33 + vloc]);
#pragma unroll
            for (int r = 0; r < 8; r++) {
                ulonglong2 a2 = *(ulonglong2*)&at[(c0 + r) * LDAT + j];
                fma2(ocp[r], a2.x, b0); fma2(ocp[r], a2.y, b1);
            }
        }
#pragma unroll
        for (int r = 0; r < 8; r++) {
            float2 p = upk2(ocp[r]);
            g_o[(size_t)(n * CH + c0 + r) * 4096 + hv * 128 + v0 + vloc] = p.x + p.y;
        }

        float egl = expf(g_glast[hv * NCH + n]);
        ull eglp = pk2(egl, egl);
        ull sp[8];
#pragma unroll
        for (int p = 0; p < 8; p++) {
            sp[p] = mul2(pk2(S[(dk0 + 2 * p) * LDS33 + vloc], S[(dk0 + 2 * p + 1) * LDS33 + vloc]), eglp);
        }
        for (int c = 0; c < 64; c++) {
            float vc = vns[c * LDS33 + vloc];
            ull bv = pk2(vc, vc);
            ulonglong2 kA = *(ulonglong2*)&kds[c * LDA + dk0];
            ulonglong2 kB = *(ulonglong2*)&kds[c * LDA + dk0 + 4];
            ulonglong2 kC = *(ulonglong2*)&kds[c * LDA + dk0 + 8];
            ulonglong2 kD = *(ulonglong2*)&kds[c * LDA + dk0 + 12];
            fma2(sp[0], kA.x, bv); fma2(sp[1], kA.y, bv);
            fma2(sp[2], kB.x, bv); fma2(sp[3], kB.y, bv);
            fma2(sp[4], kC.x, bv); fma2(sp[5], kC.y, bv);
            fma2(sp[6], kD.x, bv); fma2(sp[7], kD.y, bv);
        }
#pragma unroll
        for (int p = 0; p < 8; p++) {
            float2 v = upk2(sp[p]);
            S[(dk0 + 2 * p) * LDS33 + vloc]     = v.x;
            S[(dk0 + 2 * p + 1) * LDS33 + vloc] = v.y;
        }
        __syncthreads();
    }
}

// ================= gate (silu) + RMS norm → fp16 (warp-per-row) =================
__global__ void gate_rms_kernel(const float* __restrict__ norm_w) {
    int t = blockIdx.x;
    int w = threadIdx.x >> 5;
    int hv = blockIdx.y * 8 + w;
    int lane = threadIdx.x & 31;
    int d0 = lane * 4;

    size_t obase = (size_t)t * 4096 + hv * 128 + d0;
    float4 o4 = *(const float4*)&g_o[obase];
    float4 z4 = *(const float4*)&g_qkvz[(size_t)t * NQ + (hv >> 1) * 768 + 512 + (hv & 1) * 128 + d0];

    float v0 = o4.x * (z4.x / (1.f + __expf(-z4.x)));
    float v1 = o4.y * (z4.y / (1.f + __expf(-z4.y)));
    float v2 = o4.z * (z4.z / (1.f + __expf(-z4.z)));
    float v3 = o4.w * (z4.w / (1.f + __expf(-z4.w)));

    float ss = v0 * v0 + v1 * v1 + v2 * v2 + v3 * v3;
#pragma unroll
    for (int off = 16; off; off >>= 1) ss += __shfl_xor_sync(0xffffffffu, ss, off);
    float r = rsqrtf(ss * (1.f / 128.f) + 1e-6f);

    float4 nw = *(const float4*)&norm_w[d0];
    __half2 p0 = __floats2half2_rn(v0 * r * nw.x, v1 * r * nw.y);
    __half2 p1 = __floats2half2_rn(v2 * r * nw.z, v3 * r * nw.w);
    *(__half2*)&g_ogf[obase]     = p0;
    *(__half2*)&g_ogf[obase + 2] = p1;
}

// ================= launch =================
extern "C" void kernel_launch(void* const* d_in, const int* in_sizes, int n_in,
                              void* d_out, int out_size) {
    const float* x       = (const float*)d_in[0];
    const float* W_qkvz  = (const float*)d_in[3];
    const float* W_ba    = (const float*)d_in[4];
    const float* conv_w  = (const float*)d_in[5];
    const float* dt_bias = (const float*)d_in[6];
    const float* A_log   = (const float*)d_in[7];
    const float* norm_w  = (const float*)d_in[8];
    const float* W_out   = (const float*)d_in[9];
    float* out = (float*)d_out;

    void *p_qkvz = nullptr, *p_xf, *p_wqf, *p_wof, *p_ogf;
    cudaGetSymbolAddress(&p_qkvz, g_qkvz);
    cudaGetSymbolAddress(&p_xf, g_xf);
    cudaGetSymbolAddress(&p_wqf, g_wqf);
    cudaGetSymbolAddress(&p_wof, g_wof);
    cudaGetSymbolAddress(&p_ogf, g_ogf);

    cudaFuncSetAttribute(hgemm1,       cudaFuncAttributeMaxDynamicSharedMemorySize, HG_SMEM);
    cudaFuncSetAttribute(passA_kernel, cudaFuncAttributeMaxDynamicSharedMemorySize, PA_SMEM);
    cudaFuncSetAttribute(scan_kernel,  cudaFuncAttributeMaxDynamicSharedMemorySize, SC_SMEM);

    conv_fp16_kernel<<<(TT * 2048) / 256, 256>>>(x, (__half*)p_xf);
    tconv_kernel<<<dim3(NQ / 32, 2048 / 32), dim3(32, 8)>>>(W_qkvz, (__half*)p_wqf, 2048, NQ);
    tconv_kernel<<<dim3(2048 / 32, 4096 / 32), dim3(32, 8)>>>(W_out, (__half*)p_wof, 4096, 2048);

    // GEMM1: qkvz = x @ W_qkvz (single fp16)
    hgemm1<<<dim3(NQ / 256, TT / 128), 512, HG_SMEM>>>(
        (const __half*)p_xf, (const __half*)p_wqf, (float*)p_qkvz, TT, NQ, 2048);

    gemm_ba<<<256, 256>>>(x, W_ba);
    conv_kernel<<<(CONVD * TT) / 1024, 256>>>(conv_w);
    gbeta_kernel<<<dim3(NCH, HVN), 64>>>(dt_bias, A_log);
    passA_kernel<<<dim3(NCH, HVN), 256, PA_SMEM>>>();
    scan_kernel<<<128, 256, SC_SMEM>>>();
    gate_rms_kernel<<<dim3(TT, HVN / 8), 256>>>(norm_w);

    // GEMM3: out = og @ W_out (single fp16)
    hgemm1<<<dim3(2048 / 256, TT / 128), 512, HG_SMEM>>>(
        (const __half*)p_ogf, (const __half*)p_wof, out, TT, 2048, 4096);
}